// round 16
// baseline (speedup 1.0000x reference)
#include <cuda_runtime.h>
#include <cstdint>

#define IN_DIM   16
#define WIDTH    50
#define OUT_DIM  4
#define NL       15            // layer0 (16->50) + 14 hidden (50->50)
#define THREADS  320
#define WARPS    (THREADS/32)

// Weight layout: per (layer, ks): 16 matrices of 128B (nt 0..7 x b 0..1),
// matrix (nt,b) at (nt>>1)*512 + ((nt&1)*2+b)*128. Matrix row j (16B) =
// { W[n=nt*8+j][kinv(8ks+4b+0..3)] } as tf32-rounded fp32.
#define SZ_LAYER  14336                   // 7 ks * 2048
#define OFF_WH    0                       // 15 * 14336 = 215040
#define OFF_WO    (NL*SZ_LAYER)           // 215040: 8 ks * 2 * 128 = 2048
#define OFF_BIAS  (OFF_WO + 2048)         // 217088: [15][56] f32
#define OFF_BO    (OFF_BIAS + NL*56*4)    // 220448: [8] f32
#define SMEM_BYTES (OFF_BO + 32)          // 220480

__device__ __forceinline__ uint32_t smem_u32(const void* p) {
    uint32_t a;
    asm("{ .reg .u64 t; cvta.to.shared.u64 t, %1; cvt.u32.u64 %0, t; }" : "=r"(a) : "l"(p));
    return a;
}
__device__ __forceinline__ void ldsm4(uint32_t* r, uint32_t a) {
    asm volatile("ldmatrix.sync.aligned.m8n8.x4.shared.b16 {%0,%1,%2,%3}, [%4];"
                 : "=r"(r[0]), "=r"(r[1]), "=r"(r[2]), "=r"(r[3]) : "r"(a));
}
// tf32 MMA; A passed in prev-C register order {c0,c2,c1,c3} -> {a0,a1,a2,a3}.
// A operands are raw fp32: the tensor core ignores the low 13 mantissa bits.
__device__ __forceinline__ void mma_tf32(float* c, const float* a, uint32_t b0, uint32_t b1) {
    asm("mma.sync.aligned.m16n8k8.row.col.f32.tf32.tf32.f32 "
        "{%0,%1,%2,%3}, {%4,%5,%6,%7}, {%8,%9}, {%0,%1,%2,%3};"
        : "+f"(c[0]), "+f"(c[1]), "+f"(c[2]), "+f"(c[3])
        : "r"(__float_as_uint(a[0])), "r"(__float_as_uint(a[2])),
          "r"(__float_as_uint(a[1])), "r"(__float_as_uint(a[3])),
          "r"(b0), "r"(b1));
}
__device__ __forceinline__ float to_tf32(float v) {           // staging only (RNA)
    uint32_t u;
    asm("cvt.rna.tf32.f32 %0, %1;" : "=r"(u) : "f"(v));
    return __uint_as_float(u);
}
// kinv: neuron index feeding MMA k-slot ks (within-8-group bit permutation)
__device__ __forceinline__ int kinv(int kslot) {
    return (kslot & ~7) | ((kslot & 3) << 1) | ((kslot >> 2) & 1);
}

__device__ __forceinline__ void ld_bfrags(uint32_t* bf, uint32_t kb) {
    ldsm4(bf + 0,  kb);
    ldsm4(bf + 4,  kb + 512);
    ldsm4(bf + 8,  kb + 1024);
    ldsm4(bf + 12, kb + 1536);
}

// Dual-tile tf32 layer with double-buffered B fragments:
// C[2][7][4] = bias + A * W^T, NKS k8-steps (A extent fixed [2][7][4]).
template <int NKS>
__device__ __forceinline__ void layer_mma2(const char* sm, uint32_t sb, int layer,
                                           const float (&A)[2][7][4],
                                           float (&C)[2][7][4],
                                           int lane, uint32_t laneoff) {
    const int t = lane & 3;
    const uint32_t base = sb + OFF_WH + (uint32_t)layer * SZ_LAYER + laneoff;

    uint32_t bf[2][16];
    ld_bfrags(bf[0], base);                       // k-step 0 (independent of C/A)

    // bias init after first loads are in flight
    const float* bias = (const float*)(sm + OFF_BIAS + layer * 224);
#pragma unroll
    for (int nt = 0; nt < 7; nt++) {
        float2 bv = *(const float2*)(bias + nt * 8 + 2 * t);
#pragma unroll
        for (int tt = 0; tt < 2; tt++) {
            C[tt][nt][0] = bv.x; C[tt][nt][1] = bv.y;
            C[tt][nt][2] = bv.x; C[tt][nt][3] = bv.y;
        }
    }

#pragma unroll
    for (int ks = 0; ks < NKS; ks++) {
        if (ks + 1 < NKS)
            ld_bfrags(bf[(ks + 1) & 1], base + (uint32_t)(ks + 1) * 2048);
        const uint32_t* bc = bf[ks & 1];
#pragma unroll
        for (int tt = 0; tt < 2; tt++)
#pragma unroll
            for (int nt = 0; nt < 7; nt++)
                mma_tf32(C[tt][nt], A[tt][ks], bc[2 * nt], bc[2 * nt + 1]);
    }
}

// ReLU only — tf32 rounding is done by the tensor core (truncation of low bits)
__device__ __forceinline__ void relu_only(float (&P)[2][7][4]) {
#pragma unroll
    for (int tt = 0; tt < 2; tt++)
#pragma unroll
        for (int nt = 0; nt < 7; nt++)
#pragma unroll
            for (int q = 0; q < 4; q++)
                P[tt][nt][q] = fmaxf(P[tt][nt][q], 0.f);
}

__global__ __launch_bounds__(THREADS, 1)
void mlp_mma_kernel(const float* __restrict__ x,
                    const float* __restrict__ W0, const float* __restrict__ b0,
                    const float* __restrict__ Wh, const float* __restrict__ bh,
                    const float* __restrict__ Wo, const float* __restrict__ bo,
                    float* __restrict__ out, int n, int npairs, int nwarps) {
    extern __shared__ char sm[];
    const uint32_t sb = smem_u32(sm);
    const int tid  = threadIdx.x;
    const int wid  = tid >> 5;
    const int lane = tid & 31;

    // ---- stage hidden+first-layer weights (tf32 RNA, kinv-permuted, ldsm-transposed) ----
    for (int idx = tid; idx < NL * 3584; idx += THREADS) {
        int l  = idx / 3584;
        int f  = idx - l * 3584;
        int ks = f >> 9;
        int mat = (f >> 5) & 15;
        int w  = f & 31;
        int j  = w >> 2, tp = w & 3;
        int nt = ((mat >> 2) << 1) | ((mat >> 1) & 1);
        int b  = mat & 1;
        int nn = nt * 8 + j;
        int kslot = ks * 8 + b * 4 + tp;
        int c, Kr;
        if (l == 0) { c = kslot; Kr = IN_DIM; }
        else        { c = kinv(kslot); Kr = WIDTH; }
        float v = 0.f;
        if (nn < WIDTH && c < Kr)
            v = (l == 0) ? W0[nn * IN_DIM + c] : Wh[((l - 1) * WIDTH + nn) * WIDTH + c];
        *(float*)(sm + OFF_WH + l * SZ_LAYER + ks * 2048 + mat * 128 + j * 16 + tp * 4) = to_tf32(v);
    }
    // ---- output weights: [ks 0..7][b][128B] ----
    for (int idx = tid; idx < 512; idx += THREADS) {
        int ks = idx >> 6;
        int b  = (idx >> 5) & 1;
        int w  = idx & 31;
        int j  = w >> 2, tp = w & 3;
        int kslot = ks * 8 + b * 4 + tp;
        int c = kinv(kslot);
        float v = (j < OUT_DIM && c < WIDTH) ? Wo[j * WIDTH + c] : 0.f;
        *(float*)(sm + OFF_WO + ks * 256 + b * 128 + j * 16 + tp * 4) = to_tf32(v);
    }
    for (int idx = tid; idx < NL * 56; idx += THREADS) {
        int l = idx / 56, j = idx - l * 56;
        float f = 0.f;
        if (j < WIDTH) f = (l == 0) ? b0[j] : bh[(l - 1) * WIDTH + j];
        *(float*)(sm + OFF_BIAS + idx * 4) = f;
    }
    if (tid < 8) *(float*)(sm + OFF_BO + tid * 4) = (tid < OUT_DIM) ? bo[tid] : 0.f;
    __syncthreads();

    const int g = lane >> 2;
    const int t = lane & 3;
    const uint32_t laneoff = (uint32_t)(((lane >> 3) << 7) + ((lane & 7) << 4));

    for (int tp = blockIdx.x * WARPS + wid; tp < npairs; tp += nwarps) {
        const int base0 = tp << 5;
        float P0[2][7][4], P1[2][7][4];

        // ---- layer 0: A from x (K=16 -> 2 k8 steps, raw fp32), C -> P0 ----
        {
            float xa[2][7][4];
#pragma unroll
            for (int tt = 0; tt < 2; tt++) {
                int bb = base0 + tt * 16;
                int r0 = bb + g;     if (r0 > n - 1) r0 = n - 1;
                int r1 = bb + g + 8; if (r1 > n - 1) r1 = n - 1;
                const float* p0 = x + (size_t)r0 * IN_DIM;
                const float* p1 = x + (size_t)r1 * IN_DIM;
#pragma unroll
                for (int s = 0; s < 2; s++) {
                    xa[tt][s][0] = p0[8 * s + t];          // a0 (g,   k=8s+t)
                    xa[tt][s][2] = p1[8 * s + t];          // a1 (g+8, k=8s+t)
                    xa[tt][s][1] = p0[8 * s + 4 + t];      // a2 (g,   k=8s+4+t)
                    xa[tt][s][3] = p1[8 * s + 4 + t];      // a3 (g+8, k=8s+4+t)
                }
            }
            layer_mma2<2>(sm, sb, 0, xa, P0, lane, laneoff);
            relu_only(P0);
        }

        // ---- 14 hidden layers, ping-pong P0 <-> P1 ----
#pragma unroll 1
        for (int l = 1; l < NL; l += 2) {
            layer_mma2<7>(sm, sb, l, P0, P1, lane, laneoff);
            relu_only(P1);
            layer_mma2<7>(sm, sb, l + 1, P1, P0, lane, laneoff);
            relu_only(P0);
        }

        // ---- output layer: 50 -> 4 ----
        {
            uint32_t wb[16];
#pragma unroll
            for (int p = 0; p < 4; p++)
                ldsm4(wb + 4 * p, sb + OFF_WO + (uint32_t)p * 512 + laneoff);

            float Co[2][4];
            float2 bv = *(const float2*)(sm + OFF_BO + 2 * t * 4);
#pragma unroll
            for (int tt = 0; tt < 2; tt++) {
                Co[tt][0] = bv.x; Co[tt][1] = bv.y; Co[tt][2] = bv.x; Co[tt][3] = bv.y;
            }
#pragma unroll
            for (int ks = 0; ks < 7; ks++)
#pragma unroll
                for (int tt = 0; tt < 2; tt++)
                    mma_tf32(Co[tt], P0[tt][ks], wb[2 * ks], wb[2 * ks + 1]);

            if (t < 2) {
#pragma unroll
                for (int tt = 0; tt < 2; tt++) {
                    int bb = base0 + tt * 16;
                    int r0 = bb + g, r1 = bb + g + 8;
                    if (r0 < n) *(float2*)(out + (size_t)r0 * OUT_DIM + 2 * t) = make_float2(Co[tt][0], Co[tt][1]);
                    if (r1 < n) *(float2*)(out + (size_t)r1 * OUT_DIM + 2 * t) = make_float2(Co[tt][2], Co[tt][3]);
                }
            }
        }
    }
}

extern "C" void kernel_launch(void* const* d_in, const int* in_sizes, int n_in,
                              void* d_out, int out_size) {
    const float* x  = (const float*)d_in[0];
    const float* W0 = (const float*)d_in[1];
    const float* b0 = (const float*)d_in[2];
    const float* Wh = (const float*)d_in[3];
    const float* bh = (const float*)d_in[4];
    const float* Wo = (const float*)d_in[5];
    const float* bo = (const float*)d_in[6];
    float* out = (float*)d_out;

    int n = in_sizes[0] / IN_DIM;
    int npairs = (n + 31) >> 5;

    int sms = 148;
    cudaDeviceGetAttribute(&sms, cudaDevAttrMultiProcessorCount, 0);

    cudaFuncSetAttribute(mlp_mma_kernel, cudaFuncAttributeMaxDynamicSharedMemorySize,
                         SMEM_BYTES);

    int nwarps = sms * WARPS;
    mlp_mma_kernel<<<sms, THREADS, SMEM_BYTES>>>(x, W0, b0, Wh, bh, Wo, bo, out,
                                                 n, npairs, nwarps);
}

// round 17
// speedup vs baseline: 1.2276x; 1.2276x over previous
#include <cuda_runtime.h>
#include <cstdint>

#define IN_DIM   16
#define WIDTH    50
#define OUT_DIM  4
#define NL       15            // layer0 (16->50) + 14 hidden (50->50)
#define THREADS  384
#define WARPS    (THREADS/32)

// Weight layout: per (layer, ks): 16 matrices of 128B (nt 0..7 x b 0..1),
// matrix (nt,b) at (nt>>1)*512 + ((nt&1)*2+b)*128. Matrix row j (16B) =
// { W[n=nt*8+j][kinv(8ks+4b+0..3)] } as tf32-rounded fp32.
// k-slot 49 (padded neuron 50) carries the BIAS: neuron 50 is a constant-1
// channel (layer0 emits 1 there; each hidden layer has W[50][slot49]=1).
#define SZ_LAYER  14336                   // 7 ks * 2048
#define OFF_WH    0                       // 15 * 14336 = 215040
#define OFF_WO    (NL*SZ_LAYER)           // 215040: 8 ks * 2 * 128 = 2048
#define OFF_BIAS  (OFF_WO + 2048)         // 217088: [56] f32 (layer 0 only)
#define SMEM_BYTES (OFF_BIAS + 224)       // 217312

__device__ __forceinline__ uint32_t smem_u32(const void* p) {
    uint32_t a;
    asm("{ .reg .u64 t; cvta.to.shared.u64 t, %1; cvt.u32.u64 %0, t; }" : "=r"(a) : "l"(p));
    return a;
}
__device__ __forceinline__ void ldsm4(uint32_t* r, uint32_t a) {
    asm volatile("ldmatrix.sync.aligned.m8n8.x4.shared.b16 {%0,%1,%2,%3}, [%4];"
                 : "=r"(r[0]), "=r"(r[1]), "=r"(r[2]), "=r"(r[3]) : "r"(a));
}
// tf32 MMA; A passed in prev-C register order {c0,c2,c1,c3} -> {a0,a1,a2,a3}.
// A operands are raw fp32: the tensor core ignores the low 13 mantissa bits.
__device__ __forceinline__ void mma_tf32(float* c, const float* a, uint32_t b0, uint32_t b1) {
    asm("mma.sync.aligned.m16n8k8.row.col.f32.tf32.tf32.f32 "
        "{%0,%1,%2,%3}, {%4,%5,%6,%7}, {%8,%9}, {%0,%1,%2,%3};"
        : "+f"(c[0]), "+f"(c[1]), "+f"(c[2]), "+f"(c[3])
        : "r"(__float_as_uint(a[0])), "r"(__float_as_uint(a[2])),
          "r"(__float_as_uint(a[1])), "r"(__float_as_uint(a[3])),
          "r"(b0), "r"(b1));
}
__device__ __forceinline__ float to_tf32(float v) {           // staging only (RNA)
    uint32_t u;
    asm("cvt.rna.tf32.f32 %0, %1;" : "=r"(u) : "f"(v));
    return __uint_as_float(u);
}
// kinv: neuron index feeding MMA k-slot ks (within-8-group bit permutation)
__device__ __forceinline__ int kinv(int kslot) {
    return (kslot & ~7) | ((kslot & 3) << 1) | ((kslot >> 2) & 1);
}

// Dual-tile tf32 layer: C[2][7][4] = (bias|0) + A * W^T, NKS k8-steps
// (A extent fixed [2][7][4]). BIAS=true only for layer 0.
template <int NKS, bool BIAS>
__device__ __forceinline__ void layer_mma2(const char* sm, uint32_t sb, int layer,
                                           const float (&A)[2][7][4],
                                           float (&C)[2][7][4],
                                           int lane, uint32_t laneoff) {
    const int t = lane & 3;
    if (BIAS) {
        const float* bias = (const float*)(sm + OFF_BIAS);
#pragma unroll
        for (int nt = 0; nt < 7; nt++) {
            float2 bv = *(const float2*)(bias + nt * 8 + 2 * t);
#pragma unroll
            for (int tt = 0; tt < 2; tt++) {
                C[tt][nt][0] = bv.x; C[tt][nt][1] = bv.y;
                C[tt][nt][2] = bv.x; C[tt][nt][3] = bv.y;
            }
        }
    } else {
#pragma unroll
        for (int tt = 0; tt < 2; tt++)
#pragma unroll
            for (int nt = 0; nt < 7; nt++)
#pragma unroll
                for (int q = 0; q < 4; q++)
                    C[tt][nt][q] = 0.f;
    }
    const uint32_t base = sb + OFF_WH + (uint32_t)layer * SZ_LAYER + laneoff;
#pragma unroll
    for (int ks = 0; ks < NKS; ks++) {
        const uint32_t kb = base + (uint32_t)ks * 2048;
        uint32_t bf[16];
        ldsm4(bf + 0,  kb);
        ldsm4(bf + 4,  kb + 512);
        ldsm4(bf + 8,  kb + 1024);
        ldsm4(bf + 12, kb + 1536);
#pragma unroll
        for (int tt = 0; tt < 2; tt++)
#pragma unroll
            for (int nt = 0; nt < 7; nt++)
                mma_tf32(C[tt][nt], A[tt][ks], bf[2 * nt], bf[2 * nt + 1]);
    }
}

// ReLU only — tf32 rounding is done by the tensor core (truncation of low bits)
__device__ __forceinline__ void relu_only(float (&P)[2][7][4]) {
#pragma unroll
    for (int tt = 0; tt < 2; tt++)
#pragma unroll
        for (int nt = 0; nt < 7; nt++)
#pragma unroll
            for (int q = 0; q < 4; q++)
                P[tt][nt][q] = fmaxf(P[tt][nt][q], 0.f);
}

__global__ __launch_bounds__(THREADS, 1)
void mlp_mma_kernel(const float* __restrict__ x,
                    const float* __restrict__ W0, const float* __restrict__ b0,
                    const float* __restrict__ Wh, const float* __restrict__ bh,
                    const float* __restrict__ Wo, const float* __restrict__ bo,
                    float* __restrict__ out, int n, int npairs, int nwarps) {
    extern __shared__ char sm[];
    const uint32_t sb = smem_u32(sm);
    const int tid  = threadIdx.x;
    const int wid  = tid >> 5;
    const int lane = tid & 31;

    // ---- stage hidden+first-layer weights (tf32 RNA, kinv-permuted) ----
    // Hidden layers: k-slot 49 column = bias (nn<50), 1.0 (nn==50), 0 else.
    for (int idx = tid; idx < NL * 3584; idx += THREADS) {
        int l  = idx / 3584;
        int f  = idx - l * 3584;
        int ks = f >> 9;
        int mat = (f >> 5) & 15;
        int w  = f & 31;
        int j  = w >> 2, tp = w & 3;
        int nt = ((mat >> 2) << 1) | ((mat >> 1) & 1);
        int b  = mat & 1;
        int nn = nt * 8 + j;
        int kslot = ks * 8 + b * 4 + tp;
        float v = 0.f;
        if (l == 0) {
            if (nn < WIDTH && kslot < IN_DIM) v = W0[nn * IN_DIM + kslot];
        } else if (kslot == 49) {
            if (nn < WIDTH)      v = bh[(l - 1) * WIDTH + nn];   // bias column
            else if (nn == 50)   v = 1.f;                        // const-1 self-link
        } else {
            int c = kinv(kslot);
            if (nn < WIDTH && c < WIDTH) v = Wh[((l - 1) * WIDTH + nn) * WIDTH + c];
        }
        *(float*)(sm + OFF_WH + l * SZ_LAYER + ks * 2048 + mat * 128 + j * 16 + tp * 4) = to_tf32(v);
    }
    // ---- output weights: [ks 0..7][b][128B]; k-slot 49 = bo ----
    for (int idx = tid; idx < 512; idx += THREADS) {
        int ks = idx >> 6;
        int b  = (idx >> 5) & 1;
        int w  = idx & 31;
        int j  = w >> 2, tp = w & 3;
        int kslot = ks * 8 + b * 4 + tp;
        float v = 0.f;
        if (kslot == 49) {
            if (j < OUT_DIM) v = bo[j];
        } else {
            int c = kinv(kslot);
            if (j < OUT_DIM && c < WIDTH) v = Wo[j * WIDTH + c];
        }
        *(float*)(sm + OFF_WO + ks * 256 + b * 128 + j * 16 + tp * 4) = to_tf32(v);
    }
    // ---- layer-0 bias (neuron 50 = 1.0 to seed the constant channel) ----
    for (int idx = tid; idx < 56; idx += THREADS) {
        float f = 0.f;
        if (idx < WIDTH) f = b0[idx];
        else if (idx == 50) f = 1.f;
        *(float*)(sm + OFF_BIAS + idx * 4) = f;
    }
    __syncthreads();

    const int g = lane >> 2;
    const int t = lane & 3;
    const uint32_t laneoff = (uint32_t)(((lane >> 3) << 7) + ((lane & 7) << 4));

    for (int tp = blockIdx.x * WARPS + wid; tp < npairs; tp += nwarps) {
        const int base0 = tp << 5;
        float P0[2][7][4], P1[2][7][4];

        // ---- layer 0: A from x (K=16 -> 2 k8 steps, raw fp32), C -> P0 ----
        {
            float xa[2][7][4];
#pragma unroll
            for (int tt = 0; tt < 2; tt++) {
                int bb = base0 + tt * 16;
                int r0 = bb + g;     if (r0 > n - 1) r0 = n - 1;
                int r1 = bb + g + 8; if (r1 > n - 1) r1 = n - 1;
                const float* p0 = x + (size_t)r0 * IN_DIM;
                const float* p1 = x + (size_t)r1 * IN_DIM;
#pragma unroll
                for (int s = 0; s < 2; s++) {
                    xa[tt][s][0] = p0[8 * s + t];          // a0 (g,   k=8s+t)
                    xa[tt][s][2] = p1[8 * s + t];          // a1 (g+8, k=8s+t)
                    xa[tt][s][1] = p0[8 * s + 4 + t];      // a2 (g,   k=8s+4+t)
                    xa[tt][s][3] = p1[8 * s + 4 + t];      // a3 (g+8, k=8s+4+t)
                }
            }
            layer_mma2<2, true>(sm, sb, 0, xa, P0, lane, laneoff);
            relu_only(P0);
        }

        // ---- 14 hidden layers, ping-pong P0 <-> P1 (bias via const-1 channel) ----
#pragma unroll 1
        for (int l = 1; l < NL; l += 2) {
            layer_mma2<7, false>(sm, sb, l, P0, P1, lane, laneoff);
            relu_only(P1);
            layer_mma2<7, false>(sm, sb, l + 1, P1, P0, lane, laneoff);
            relu_only(P0);
        }

        // ---- output layer: 50 -> 4 (bias via const-1 channel) ----
        {
            uint32_t wb[16];
#pragma unroll
            for (int p = 0; p < 4; p++)
                ldsm4(wb + 4 * p, sb + OFF_WO + (uint32_t)p * 512 + laneoff);

            float Co[2][4];
#pragma unroll
            for (int tt = 0; tt < 2; tt++) {
                Co[tt][0] = 0.f; Co[tt][1] = 0.f; Co[tt][2] = 0.f; Co[tt][3] = 0.f;
            }
#pragma unroll
            for (int ks = 0; ks < 7; ks++)
#pragma unroll
                for (int tt = 0; tt < 2; tt++)
                    mma_tf32(Co[tt], P0[tt][ks], wb[2 * ks], wb[2 * ks + 1]);

            if (t < 2) {
#pragma unroll
                for (int tt = 0; tt < 2; tt++) {
                    int bb = base0 + tt * 16;
                    int r0 = bb + g, r1 = bb + g + 8;
                    if (r0 < n) *(float2*)(out + (size_t)r0 * OUT_DIM + 2 * t) = make_float2(Co[tt][0], Co[tt][1]);
                    if (r1 < n) *(float2*)(out + (size_t)r1 * OUT_DIM + 2 * t) = make_float2(Co[tt][2], Co[tt][3]);
                }
            }
        }
    }
}

extern "C" void kernel_launch(void* const* d_in, const int* in_sizes, int n_in,
                              void* d_out, int out_size) {
    const float* x  = (const float*)d_in[0];
    const float* W0 = (const float*)d_in[1];
    const float* b0 = (const float*)d_in[2];
    const float* Wh = (const float*)d_in[3];
    const float* bh = (const float*)d_in[4];
    const float* Wo = (const float*)d_in[5];
    const float* bo = (const float*)d_in[6];
    float* out = (float*)d_out;

    int n = in_sizes[0] / IN_DIM;
    int npairs = (n + 31) >> 5;

    int sms = 148;
    cudaDeviceGetAttribute(&sms, cudaDevAttrMultiProcessorCount, 0);

    cudaFuncSetAttribute(mlp_mma_kernel, cudaFuncAttributeMaxDynamicSharedMemorySize,
                         SMEM_BYTES);

    int nwarps = sms * WARPS;
    mlp_mma_kernel<<<sms, THREADS, SMEM_BYTES>>>(x, W0, b0, Wh, bh, Wo, bo, out,
                                                 n, npairs, nwarps);
}